// round 17
// baseline (speedup 1.0000x reference)
#include <cuda_runtime.h>
#include <cuda_fp16.h>
#include <cstdint>

#define T_IN 16
#define T_OUT 25
#define NB 4096
#define KN 32
#define NNBR (NB*KN)
#define ENC 64
#define DEC 128
#define DYN 32
#define EMB 32
#define FHL 16

typedef unsigned long long u64;

// -------- scratch --------
__device__ __align__(16) float g_Wd4[4*DEC*(2*DYN)];        // quad-transposed Wih_d
__device__ __align__(16) uint4 g_A[32*8*2*32];              // dec Whh_d frags (hi/lo)
__device__ __align__(16) uint4 g_Ae[16*6*2*32];             // enc [Whh_e|Wih_e] frags (hi/lo)

__device__ __forceinline__ float lrelu(float x){ return x >= 0.f ? x : 0.1f*x; }
__device__ __forceinline__ float tanha(float x){
    float r; asm("tanh.approx.f32 %0, %1;" : "=f"(r) : "f"(x)); return r;
}
__device__ __forceinline__ float sig_t(float x){ return fmaf(0.5f, tanha(0.5f*x), 0.5f); }

__device__ __forceinline__ void fma2(u64& d, u64 a, u64 b){
    asm("fma.rn.f32x2 %0, %1, %2, %0;" : "+l"(d) : "l"(a), "l"(b));
}
__device__ __forceinline__ u64 packf2(float x, float y){
    u64 r; asm("mov.b64 %0, {%1,%2};" : "=l"(r) : "f"(x), "f"(y)); return r;
}
__device__ __forceinline__ float red2(u64 a){
    float x, y; asm("mov.b64 {%0,%1}, %2;" : "=f"(x), "=f"(y) : "l"(a)); return x + y;
}
__device__ __forceinline__ u64 lo2(float x){ return (u64)__float_as_uint(x); }

#define MMA(d, a, bx, by) \
    asm volatile("mma.sync.aligned.m16n8k16.row.col.f32.f16.f16.f32 " \
        "{%0,%1,%2,%3},{%4,%5,%6,%7},{%8,%9},{%0,%1,%2,%3};" \
        : "+f"((d)[0]), "+f"((d)[1]), "+f"((d)[2]), "+f"((d)[3]) \
        : "r"((a).x), "r"((a).y), "r"((a).z), "r"((a).w), "r"(bx), "r"(by))

__device__ __forceinline__ unsigned ph2(float a, float b, int hl){
    __half ah = __float2half_rn(a), bh = __float2half_rn(b);
    __half x = hl ? __float2half_rn(a - __half2float(ah)) : ah;
    __half y = hl ? __float2half_rn(b - __half2float(bh)) : bh;
    return (unsigned)__half_as_ushort(x) | ((unsigned)__half_as_ushort(y) << 16);
}

// encoder B store (hi+lo, 12-float row, 2 nbl blocks of 16B; uint4 loads conflict-free)
__device__ __forceinline__ void bfrag_storeE(float* Bn, int k, int n, float v){
    __half hhi = __float2half_rn(v);
    __half hlo = __float2half_rn(v - __half2float(hhi));
    int ks2 = k >> 4, kk = k & 15;
    int rg = kk >> 3, ctq = (kk & 7) >> 1, dl = kk & 1;
    int lp = (n & 7)*4 + ctq, nbl = n >> 3;
    char* bptr = (char*)(Bn + (ks2*32 + lp)*12) + nbl*16 + rg*4 + dl*2;
    *(__half*)bptr = hhi;
    *(__half*)(bptr + 8) = hlo;
}
// decoder B store (hi-only, 4-float row = contiguous; LDS.128 fully coalesced)
__device__ __forceinline__ void bfrag_storeD(float* Bn, int k, int n, float v){
    __half hhi = __float2half_rn(v);
    int ks2 = k >> 4, kk = k & 15;
    int rg = kk >> 3, ctq = (kk & 7) >> 1, dl = kk & 1;
    int lp = (n & 7)*4 + ctq, nbl = n >> 3;
    char* bptr = (char*)(Bn + (ks2*32 + lp)*4) + nbl*8 + rg*4 + dl*2;
    *(__half*)bptr = hhi;
}

// ============================================================
// Kernel 0: fragment weights, gate-pair interleave (unchanged).
// ============================================================
__global__ void prep_kernel(const float* __restrict__ WhhD, const float* __restrict__ WihD,
                            const float* __restrict__ WhhE, const float* __restrict__ WihE)
{
    int idx = blockIdx.x*256 + threadIdx.x;
    if (idx < 16384) {
        int mt = idx >> 9, ks = (idx >> 6) & 7, hl = (idx >> 5) & 1, l = idx & 31;
        int gr = l >> 2, ct = l & 3;
        int unit = 4*mt + (gr >> 1);
        int r0 = (gr & 1)*128 + unit;
        int r1 = r0 + 256;
        int k0 = 16*ks + 2*ct;
        uint4 v;
        v.x = ph2(WhhD[r0*128 + k0],     WhhD[r0*128 + k0 + 1], hl);
        v.y = ph2(WhhD[r1*128 + k0],     WhhD[r1*128 + k0 + 1], hl);
        v.z = ph2(WhhD[r0*128 + k0 + 8], WhhD[r0*128 + k0 + 9], hl);
        v.w = ph2(WhhD[r1*128 + k0 + 8], WhhD[r1*128 + k0 + 9], hl);
        g_A[((mt*8 + ks)*2 + hl)*32 + l] = v;
    } else if (idx < 24576) {
        int j = idx - 16384;
        int k4 = j >> 9, r = j & 511;
        float4 v = *(const float4*)(WihD + r*(2*DYN) + k4*4);
        *(float4*)(g_Wd4 + ((size_t)k4*512 + r)*4) = v;
    } else {
        int j2 = idx - 24576;
        int mt = j2 / 384;
        int rem = j2 - mt*384;
        int ks = rem >> 6, hl = (rem >> 5) & 1, l = rem & 31;
        int gr = l >> 2, ct = l & 3;
        int unit = 4*mt + (gr >> 1);
        int g0 = gr & 1, g1 = g0 + 2;
        int k0 = 16*ks + 2*ct;
        auto W = [&](int gate, int k) -> float {
            int row = gate*64 + unit;
            return (k < 64) ? WhhE[row*64 + k] : WihE[row*32 + (k - 64)];
        };
        uint4 v;
        v.x = ph2(W(g0,k0),   W(g0,k0+1), hl);
        v.y = ph2(W(g1,k0),   W(g1,k0+1), hl);
        v.z = ph2(W(g0,k0+8), W(g0,k0+9), hl);
        v.w = ph2(W(g1,k0+8), W(g1,k0+9), hl);
        g_Ae[((mt*6 + ks)*2 + hl)*32 + l] = v;
    }
}

// ============================================================
// FUSED kernel. 16 heroes/block, 256 threads, grid 256, occupancy 2.
// smem ~92 KB -> 2 CTAs/SM, single wave (256 <= 296 slots).
// ============================================================
__global__ void __launch_bounds__(256, 2) fused_kernel(
        const float* __restrict__ hist, const float* __restrict__ nbrs,
        const float* __restrict__ Wip,  const float* __restrict__ bip,
        const float* __restrict__ bih,  const float* __restrict__ bhh,
        const float* __restrict__ Wdyn, const float* __restrict__ bdyn,
        const float* __restrict__ Wnbr, const float* __restrict__ bnbr,
        const float* __restrict__ bih_d,const float* __restrict__ bhh_d,
        const float* __restrict__ Wop,  const float* __restrict__ bop,
        const int* __restrict__ seg,    float* __restrict__ out)
{
    extern __shared__ __align__(16) float sm[];
    float* sPre = sm;              // [512][17] 8704
    float* sMax = sm + 8704;       // [16][64] 1024
    float* sHT  = sMax + 1024;     // [64][17] 1088
    float* sWk  = sHT + 1088;      // 2112 overlay: Wnbr+bnbr / WdynT
    float* sEnc = sWk + 2112;      // [16][64] 1024
    float* sBb  = sEnc + 1024;     // 4608: encB 2x2304 | decB 2x1024
    float* sHf  = sBb + 4608;      // [2][16][130] 4160
    float* sWop = sHf + 4160;      // 256

    int tid = threadIdx.x;
    int b0 = blockIdx.x * FHL;
    int warp = tid >> 5, lane = tid & 31;
    int gr = lane >> 2, ct = lane & 3;
    int jx = gr & 1, ul = gr >> 1;

    // ---------------- Phase A: neighbor MLP + segment max ----------------
    for (int i = tid; i < 2112; i += 256) sWk[i] = (i < 2048) ? Wnbr[i] : bnbr[i - 2048];
    __syncthreads();
#pragma unroll
    for (int p = 0; p < 2; ++p) {
        int hero = warp + p*8;                 // 0..15
        int n = (b0 + hero)*KN + lane;
        int sgid = seg[n];
        u64 xp[16];
#pragma unroll
        for (int t = 0; t < T_IN; ++t) {
            float2 hv = *(const float2*)(hist + ((size_t)t*NB + sgid)*2);
            float2 nv = *(const float2*)(nbrs + ((size_t)t*NNBR + n)*2);
            xp[t] = packf2(hv.x - nv.x, hv.y - nv.y);
        }
#pragma unroll 4
        for (int g = 0; g < ENC; ++g) {
            u64 a2 = lo2(sWk[2048 + g]);
            const ulonglong2* w = (const ulonglong2*)(sWk + g*32);
#pragma unroll
            for (int k = 0; k < 8; ++k) {
                ulonglong2 wv = w[k];
                fma2(a2, wv.x, xp[2*k]);
                fma2(a2, wv.y, xp[2*k+1]);
            }
            float acc = lrelu(red2(a2));
#pragma unroll
            for (int off = 16; off; off >>= 1)
                acc = fmaxf(acc, __shfl_xor_sync(0xffffffffu, acc, off));
            if (lane == 0) sMax[hero*ENC + g] = acc;
        }
    }
    __syncthreads();

    // ---------------- Phase B: HMMA encoder (2-term), shfl epilogue ----------------
    for (int i = tid; i < 4608; i += 256) sBb[i] = 0.f;
    // enc: 8 warps x 2 M-tiles (mt = warp + 8m), N=16 -> nb in {0,1}
    float bsum[4][2];
#pragma unroll
    for (int m = 0; m < 2; ++m) {
        int unit = 4*(warp + 8*m) + ul;
#pragma unroll
        for (int g = 0; g < 4; ++g)
            bsum[g][m] = __ldg(bih + g*64 + unit) + __ldg(bhh + g*64 + unit);
    }
    // emb: thread -> hero nn = tid&15, j pair = 2*(tid>>4), +1
    int nn = tid & 15;
    int jp = tid >> 4;           // 0..15
    float wj0[2], wj1[2], bj[2];
#pragma unroll
    for (int jj = 0; jj < 2; ++jj) {
        int j = jp*2 + jj;
        wj0[jj] = Wip[j*2]; wj1[jj] = Wip[j*2+1]; bj[jj] = bip[j];
    }
    float cE[4];
#pragma unroll
    for (int i = 0; i < 4; ++i) cE[i] = 0.f;
    __syncthreads();
    {
        float2 hv = *(const float2*)(hist + ((size_t)(b0 + nn))*2);
#pragma unroll
        for (int jj = 0; jj < 2; ++jj) {
            float e = lrelu(fmaf(wj0[jj], hv.x, fmaf(wj1[jj], hv.y, bj[jj])));
            bfrag_storeE(sBb, 64 + jp*2 + jj, nn, e);
        }
    }
    __syncthreads();

#pragma unroll 1
    for (int t = 0; t < T_IN; ++t) {
        float* Bc = sBb + (t & 1)*2304;
        float* Bn = sBb + ((t & 1) ^ 1)*2304;
        float acc[2][2][4];
#pragma unroll
        for (int m = 0; m < 2; ++m)
#pragma unroll
            for (int nb = 0; nb < 2; ++nb)
#pragma unroll
                for (int r = 0; r < 4; ++r) acc[m][nb][r] = 0.f;
#pragma unroll
        for (int ks = 0; ks < 6; ++ks) {
            const uint4* bp = (const uint4*)(Bc + (ks*32 + lane)*12);
            uint4 bv[2];
            bv[0] = bp[0]; bv[1] = bp[1];
#pragma unroll
            for (int m = 0; m < 2; ++m) {
                int mt = warp + 8*m;
                uint4 ahi = __ldg(&g_Ae[((mt*6 + ks)*2 + 0)*32 + lane]);
#pragma unroll
                for (int nb = 0; nb < 2; ++nb) {
                    MMA(acc[m][nb], ahi, bv[nb].x, bv[nb].y);
                    MMA(acc[m][nb], ahi, bv[nb].z, bv[nb].w);
                }
            }
        }
#pragma unroll
        for (int m = 0; m < 2; ++m) {
            int unit = 4*(warp + 8*m) + ul;
#pragma unroll
            for (int nb = 0; nb < 2; ++nb) {
                float c0 = acc[m][nb][0], c1 = acc[m][nb][1];
                float c2 = acc[m][nb][2], c3 = acc[m][nb][3];
                float sAv = jx ? c0 : c1;
                float sBv = jx ? c2 : c3;
                float rA = __shfl_xor_sync(0xffffffffu, sAv, 4);
                float rB = __shfl_xor_sync(0xffffffffu, sBv, 4);
                float g0 = jx ? rA : c0;
                float g1 = jx ? c1 : rA;
                float g2 = jx ? rB : c2;
                float g3 = jx ? c3 : rB;
                int it = m*2 + nb;
                float gi = g0 + bsum[0][m];
                float gf = g1 + bsum[1][m];
                float gg = g2 + bsum[2][m];
                float go = g3 + bsum[3][m];
                cE[it] = fmaf(sig_t(gf), cE[it], sig_t(gi)*tanha(gg));
                float hv = sig_t(go)*tanha(cE[it]);
                int hero = 8*nb + 2*ct + jx;
                bfrag_storeE(Bn, unit, hero, hv);
                if (t == T_IN - 1) sHT[unit*17 + hero] = hv;
            }
        }
        if (t < T_IN - 1) {
            float2 hv2 = *(const float2*)(hist + ((size_t)(t+1)*NB + b0 + nn)*2);
#pragma unroll
            for (int jj = 0; jj < 2; ++jj) {
                float e = lrelu(fmaf(wj0[jj], hv2.x, fmaf(wj1[jj], hv2.y, bj[jj])));
                bfrag_storeE(Bn, 64 + jp*2 + jj, nn, e);
            }
        }
        __syncthreads();
    }

    // ---------------- Phase C: Wdyn projections + dec-input GEMM ----------------
    for (int i = tid; i < DYN*ENC; i += 256) {
        int r = i >> 6, cc = i & 63;
        sWk[cc*32 + r] = Wdyn[i];
    }
    __syncthreads();
#pragma unroll
    for (int pass = 0; pass < 4; ++pass) {
        int it = tid + pass*256;          // 1024 items = 16 heroes x 64 outputs
        int hero = it >> 6, o = it & 63;
        int row = o & 31;
        float a = __ldg(bdyn + row);
        if (o < 32) {
#pragma unroll 8
            for (int k = 0; k < 64; ++k) a = fmaf(sWk[k*32 + row], sHT[k*17 + hero], a);
        } else {
#pragma unroll 8
            for (int k = 0; k < 64; ++k) a = fmaf(sWk[k*32 + row], sMax[hero*64 + k], a);
        }
        sEnc[hero*64 + o] = lrelu(a);
    }
    __syncthreads();
#pragma unroll
    for (int rp = 0; rp < 2; ++rp) {
        int r = tid + rp*256;
        float bs = __ldg(bih_d + r) + __ldg(bhh_d + r);
        u64 acc2[16];
#pragma unroll
        for (int hl = 0; hl < 16; ++hl) acc2[hl] = lo2(bs);
#pragma unroll 4
        for (int k4 = 0; k4 < 16; ++k4) {
            ulonglong2 w = *(const ulonglong2*)(g_Wd4 + ((size_t)k4*512 + r)*4);
#pragma unroll
            for (int hl = 0; hl < 16; ++hl) {
                ulonglong2 e = *(const ulonglong2*)(sEnc + hl*64 + k4*4);
                fma2(acc2[hl], w.x, e.x);
                fma2(acc2[hl], w.y, e.y);
            }
        }
#pragma unroll
        for (int hl = 0; hl < 16; ++hl)
            sPre[r*17 + hl] = red2(acc2[hl]);
    }
    // zero dec B buffers (2 x 1024), load Wop
    for (int i = tid; i < 2048; i += 256) sBb[i] = 0.f;
    for (int i = tid; i < 256; i += 256) sWop[i] = Wop[i];
    __syncthreads();

    // ---------------- Dec phase: HMMA decoder (1-term), shfl epilogue ----------------
    // 8 warps x 4 M-tiles (mt = warp + 8m), N=16 -> nb in {0,1}; 8 items/thread.
    float pre[4][8];
#pragma unroll
    for (int m = 0; m < 4; ++m) {
        int unit = 4*(warp + 8*m) + ul;
#pragma unroll
        for (int nb = 0; nb < 2; ++nb) {
            int hero = 8*nb + 2*ct + jx;
#pragma unroll
            for (int g = 0; g < 4; ++g)
                pre[g][m*2+nb] = sPre[(g*128 + unit)*17 + hero];
        }
    }
    float c[8];
#pragma unroll
    for (int i = 0; i < 8; ++i) c[i] = 0.f;
    __syncthreads();

    for (int t = 0; t < T_OUT; ++t) {
        const float* Bc = sBb + (t & 1)*1024;
        float* Bn = sBb + ((t & 1) ^ 1)*1024;
        float* sHfW = sHf + (t & 1)*2080;

        float acc[4][2][4];
#pragma unroll
        for (int m = 0; m < 4; ++m)
#pragma unroll
            for (int nb = 0; nb < 2; ++nb)
#pragma unroll
                for (int r = 0; r < 4; ++r) acc[m][nb][r] = 0.f;

#pragma unroll
        for (int ks = 0; ks < 8; ++ks) {
            uint4 q = *(const uint4*)(Bc + (ks*32 + lane)*4);
            uint2 bv[2];
            bv[0] = make_uint2(q.x, q.y);
            bv[1] = make_uint2(q.z, q.w);
#pragma unroll
            for (int m = 0; m < 4; ++m) {
                int mt = warp + 8*m;
                uint4 ahi = __ldg(&g_A[((mt*8 + ks)*2 + 0)*32 + lane]);
#pragma unroll
                for (int nb = 0; nb < 2; ++nb)
                    MMA(acc[m][nb], ahi, bv[nb].x, bv[nb].y);
            }
        }
#pragma unroll
        for (int m = 0; m < 4; ++m) {
            int unit = 4*(warp + 8*m) + ul;
#pragma unroll
            for (int nb = 0; nb < 2; ++nb) {
                float c0 = acc[m][nb][0], c1 = acc[m][nb][1];
                float c2 = acc[m][nb][2], c3 = acc[m][nb][3];
                float sAv = jx ? c0 : c1;
                float sBv = jx ? c2 : c3;
                float rA = __shfl_xor_sync(0xffffffffu, sAv, 4);
                float rB = __shfl_xor_sync(0xffffffffu, sBv, 4);
                float g0 = jx ? rA : c0;
                float g1 = jx ? c1 : rA;
                float g2 = jx ? rB : c2;
                float g3 = jx ? c3 : rB;
                int it = m*2 + nb;
                float gi = g0 + pre[0][it];
                float gf = g1 + pre[1][it];
                float gg = g2 + pre[2][it];
                float go = g3 + pre[3][it];
                c[it] = fmaf(sig_t(gf), c[it], sig_t(gi)*tanha(gg));
                float hv = sig_t(go)*tanha(c[it]);
                int hero = 8*nb + 2*ct + jx;
                sHfW[hero*130 + unit] = hv;
                bfrag_storeD(Bn, unit, hero, hv);
            }
        }
        __syncthreads();
        if (tid < 32) {
            int hero = tid >> 1, d = tid & 1;
            u64 a2 = lo2(__ldg(bop + d));
            const u64* wo = (const u64*)(sWop + d*128);
            const u64* hr = (const u64*)(sHfW + hero*130);
#pragma unroll
            for (int k2 = 0; k2 < 64; ++k2) fma2(a2, wo[k2], hr[k2]);
            out[(size_t)t*NB*2 + (size_t)(b0 + hero)*2 + d] = red2(a2);
        }
    }
}

// ============================================================
extern "C" void kernel_launch(void* const* d_in, const int* in_sizes, int n_in,
                              void* d_out, int out_size)
{
    const float* hist  = (const float*)d_in[0];
    const float* nbrs  = (const float*)d_in[1];
    const float* Wip   = (const float*)d_in[2];
    const float* bip   = (const float*)d_in[3];
    const float* Wih_e = (const float*)d_in[4];
    const float* Whh_e = (const float*)d_in[5];
    const float* bih_e = (const float*)d_in[6];
    const float* bhh_e = (const float*)d_in[7];
    const float* Wdyn  = (const float*)d_in[8];
    const float* bdyn  = (const float*)d_in[9];
    const float* Wnbr  = (const float*)d_in[10];
    const float* bnbr  = (const float*)d_in[11];
    const float* Wih_d = (const float*)d_in[12];
    const float* Whh_d = (const float*)d_in[13];
    const float* bih_d = (const float*)d_in[14];
    const float* bhh_d = (const float*)d_in[15];
    const float* Wop   = (const float*)d_in[16];
    const float* bop   = (const float*)d_in[17];
    const int*   seg   = (const int*)d_in[18];
    float* out = (float*)d_out;

    constexpr int FUSED_SMEM = (8704 + 1024 + 1088 + 2112 + 1024 + 4608 + 4160 + 256)
                               * (int)sizeof(float);   // 91904 B
    cudaFuncSetAttribute(fused_kernel, cudaFuncAttributeMaxDynamicSharedMemorySize, FUSED_SMEM);

    prep_kernel<<<120, 256>>>(Whh_d, Wih_d, Whh_e, Wih_e);
    fused_kernel<<<NB/FHL, 256, FUSED_SMEM>>>(hist, nbrs, Wip, bip,
                                              bih_e, bhh_e, Wdyn, bdyn, Wnbr, bnbr,
                                              bih_d, bhh_d, Wop, bop, seg, out);
}